// round 3
// baseline (speedup 1.0000x reference)
#include <cuda_runtime.h>
#include <cuda_bf16.h>
#include <math.h>
#include <stdint.h>

// Problem constants (B=1)
#define S_LEN  2048
#define DMODEL 2048
#define NHEADS 16
#define HD     128
#define KVH    4
#define KVD    512   // KVH*HD

// ---------------- scratch (no allocations allowed) ----------------
__device__ float g_q[S_LEN * DMODEL];            // q proj -> normed+roped in place
__device__ float g_k[S_LEN * KVD];               // k proj -> normed+roped in place
__device__ float g_v[S_LEN * KVD];               // v proj
__device__ float g_y[S_LEN * DMODEL];            // attention output
__device__ float g_s[(size_t)NHEADS * S_LEN * S_LEN];  // scores / probs (268 MB)

// =============================================================
// GEMM (NT): C[M,N] = A[M,K] * B[N,K]^T, row-major fp32.
// 128x128 tile, BK=16, 256 threads, 8x8 microtile.
// =============================================================
__global__ void __launch_bounds__(256, 2)
gemm_nt_kernel(const float* __restrict__ A, const float* __restrict__ B,
               float* __restrict__ C, int M, int N, int K)
{
    __shared__ float As[16][132];
    __shared__ float Bs[16][132];

    const int tid = threadIdx.x;
    const int tx = tid & 15;
    const int ty = tid >> 4;

    const float* Ab = A + (size_t)blockIdx.y * 128 * K;
    const float* Bb = B + (size_t)blockIdx.x * 128 * K;

    float acc[8][8];
#pragma unroll
    for (int i = 0; i < 8; i++)
#pragma unroll
        for (int j = 0; j < 8; j++) acc[i][j] = 0.f;

    for (int k0 = 0; k0 < K; k0 += 16) {
#pragma unroll
        for (int i = 0; i < 2; i++) {
            int idx = tid + i * 256;
            int row = idx >> 2;
            int cg  = idx & 3;
            float4 a4 = *(const float4*)(Ab + (size_t)row * K + k0 + cg * 4);
            As[cg * 4 + 0][row] = a4.x;
            As[cg * 4 + 1][row] = a4.y;
            As[cg * 4 + 2][row] = a4.z;
            As[cg * 4 + 3][row] = a4.w;
            float4 b4 = *(const float4*)(Bb + (size_t)row * K + k0 + cg * 4);
            Bs[cg * 4 + 0][row] = b4.x;
            Bs[cg * 4 + 1][row] = b4.y;
            Bs[cg * 4 + 2][row] = b4.z;
            Bs[cg * 4 + 3][row] = b4.w;
        }
        __syncthreads();

#pragma unroll
        for (int k = 0; k < 16; k++) {
            float a[8], b[8];
            *(float4*)&a[0] = *(const float4*)&As[k][ty * 8];
            *(float4*)&a[4] = *(const float4*)&As[k][ty * 8 + 4];
            *(float4*)&b[0] = *(const float4*)&Bs[k][tx * 8];
            *(float4*)&b[4] = *(const float4*)&Bs[k][tx * 8 + 4];
#pragma unroll
            for (int i = 0; i < 8; i++)
#pragma unroll
                for (int j = 0; j < 8; j++)
                    acc[i][j] += a[i] * b[j];
        }
        __syncthreads();
    }

    float* Cb = C + (size_t)(blockIdx.y * 128 + ty * 8) * N + blockIdx.x * 128 + tx * 8;
#pragma unroll
    for (int i = 0; i < 8; i++) {
        *(float4*)(Cb + (size_t)i * N)     = make_float4(acc[i][0], acc[i][1], acc[i][2], acc[i][3]);
        *(float4*)(Cb + (size_t)i * N + 4) = make_float4(acc[i][4], acc[i][5], acc[i][6], acc[i][7]);
    }
}

// =============================================================
// RMSNorm + RoPE v2: ONE WARP per (s, head). Pure warp shuffles.
// lane l handles freq indices i = 2l and 2l+1:
//   x1 = elem[i], x2 = elem[i+64], theta_i = s * 10000^(-2i/128)
//   out[i]    = x1*cos + x2*sin
//   out[i+64] = x2*cos - x1*sin
// =============================================================
__global__ void rope2_kernel(float* __restrict__ buf, int rowstride, int nheads,
                             const float* __restrict__ gain)
{
    const int w    = blockIdx.x * (blockDim.x >> 5) + (threadIdx.x >> 5);
    const int lane = threadIdx.x & 31;
    const int s = w / nheads;
    const int h = w % nheads;
    if (s >= S_LEN) return;

    float* p = buf + (size_t)s * rowstride + h * HD;

    float2 u1 = *(const float2*)(p + 2 * lane);        // elems 2l, 2l+1
    float2 u2 = *(const float2*)(p + 64 + 2 * lane);   // elems 64+2l, 64+2l+1

    float ss = u1.x * u1.x + u1.y * u1.y + u2.x * u2.x + u2.y * u2.y;
#pragma unroll
    for (int off = 16; off; off >>= 1)
        ss += __shfl_xor_sync(0xffffffffu, ss, off);

    const float r = rsqrtf(ss * (1.f / 128.f) + 1.1920929e-07f);
    const float g = gain ? gain[h] : 1.0f;

    float x1a = u1.x * r, x1b = u1.y * r;   // x1 at i0=2l, i1=2l+1
    float x2a = u2.x * r, x2b = u2.y * r;   // x2 at i0,   i1

    // theta = s * exp(-(2*i/128) * ln(10000))
    const float kln = 9.210340371976184f / 128.f;   // ln(10000)/128
    float th0 = (float)s * expf(-(float)(2 * (2 * lane))     * kln);
    float th1 = (float)s * expf(-(float)(2 * (2 * lane + 1)) * kln);
    float c0, s0, c1, s1;
    sincosf(th0, &s0, &c0);
    sincosf(th1, &s1, &c1);

    float o1a = x1a * c0 + x2a * s0;
    float o1b = x1b * c1 + x2b * s1;
    float o2a = x2a * c0 - x1a * s0;
    float o2b = x2b * c1 - x1b * s1;

    *(float2*)(p + 2 * lane)      = make_float2(o1a * g, o1b * g);
    *(float2*)(p + 64 + 2 * lane) = make_float2(o2a * g, o2b * g);
}

// =============================================================
// Phase 1: scores. One block per (qb, kb, h), kb <= qb.
// 64x64 tile, scaled by 1/sqrt(128), written to g_s (full tile,
// including j>i on the diagonal tile — softmax never reads those).
// smem: QsT[128][64], KsT[128][64]  (transposed: [k][row])
// =============================================================
#define SCORE_SMEM (2 * 128 * 64 * 4)

__global__ void __launch_bounds__(256)
score_kernel()
{
    const int qb = blockIdx.x;
    const int kb = blockIdx.y;
    const int h  = blockIdx.z;
    if (kb > qb) return;

    extern __shared__ float sm[];
    float* QsT = sm;          // [128][64]
    float* KsT = sm + 8192;   // [128][64]

    const int tid = threadIdx.x;
    const int tx = tid & 15;   // col group: cols 4tx..4tx+3
    const int ty = tid >> 4;   // row group: rows 4ty..4ty+3

    const float* Qg = g_q + (size_t)(qb * 64) * DMODEL + h * HD;
    const float* Kg = g_k + (size_t)(kb * 64) * KVD + (h >> 2) * HD;

#pragma unroll
    for (int i = 0; i < 8; i++) {
        int idx = tid + i * 256;     // 0..2047 = 64 rows x 32 kgroups
        int row = idx >> 5;
        int kg  = idx & 31;
        float4 q4 = *(const float4*)(Qg + (size_t)row * DMODEL + kg * 4);
        QsT[(kg * 4 + 0) * 64 + row] = q4.x;
        QsT[(kg * 4 + 1) * 64 + row] = q4.y;
        QsT[(kg * 4 + 2) * 64 + row] = q4.z;
        QsT[(kg * 4 + 3) * 64 + row] = q4.w;
        float4 k4 = *(const float4*)(Kg + (size_t)row * KVD + kg * 4);
        KsT[(kg * 4 + 0) * 64 + row] = k4.x;
        KsT[(kg * 4 + 1) * 64 + row] = k4.y;
        KsT[(kg * 4 + 2) * 64 + row] = k4.z;
        KsT[(kg * 4 + 3) * 64 + row] = k4.w;
    }
    __syncthreads();

    float acc[4][4];
#pragma unroll
    for (int i = 0; i < 4; i++)
#pragma unroll
        for (int j = 0; j < 4; j++) acc[i][j] = 0.f;

#pragma unroll 4
    for (int k = 0; k < HD; k++) {
        float a0 = QsT[k * 64 + 4 * ty + 0];
        float a1 = QsT[k * 64 + 4 * ty + 1];
        float a2 = QsT[k * 64 + 4 * ty + 2];
        float a3 = QsT[k * 64 + 4 * ty + 3];
        float b0 = KsT[k * 64 + 4 * tx + 0];
        float b1 = KsT[k * 64 + 4 * tx + 1];
        float b2 = KsT[k * 64 + 4 * tx + 2];
        float b3 = KsT[k * 64 + 4 * tx + 3];
        acc[0][0] += a0 * b0; acc[0][1] += a0 * b1; acc[0][2] += a0 * b2; acc[0][3] += a0 * b3;
        acc[1][0] += a1 * b0; acc[1][1] += a1 * b1; acc[1][2] += a1 * b2; acc[1][3] += a1 * b3;
        acc[2][0] += a2 * b0; acc[2][1] += a2 * b1; acc[2][2] += a2 * b2; acc[2][3] += a2 * b3;
        acc[3][0] += a3 * b0; acc[3][1] += a3 * b1; acc[3][2] += a3 * b2; acc[3][3] += a3 * b3;
    }

    const float scale = 0.08838834764831845f;  // 1/sqrt(128)
    float* Sg = g_s + ((size_t)h * S_LEN + (size_t)qb * 64) * S_LEN + kb * 64;
#pragma unroll
    for (int i = 0; i < 4; i++)
#pragma unroll
        for (int j = 0; j < 4; j++)
            Sg[(size_t)(4 * ty + i) * S_LEN + 4 * tx + j] = acc[i][j] * scale;
}

// =============================================================
// Phase 2: softmax per (row i, head h) over j in [0, i] only.
// Then zero the diagonal-tile tail (i+1 .. next multiple of 64 - 1)
// so phase 3 can consume full tiles without predicates.
// =============================================================
__global__ void __launch_bounds__(128)
softmax_kernel()
{
    const int i = blockIdx.x;
    const int h = blockIdx.y;
    float* base = g_s + ((size_t)h * S_LEN + i) * S_LEN;
    const int n = i + 1;

    const int tid = threadIdx.x;
    const int lane = tid & 31, w = tid >> 5;
    __shared__ float red[4];

    // max
    float m = -INFINITY;
    for (int j = tid; j < n; j += 128) m = fmaxf(m, base[j]);
#pragma unroll
    for (int off = 16; off; off >>= 1)
        m = fmaxf(m, __shfl_xor_sync(0xffffffffu, m, off));
    if (lane == 0) red[w] = m;
    __syncthreads();
    m = fmaxf(fmaxf(red[0], red[1]), fmaxf(red[2], red[3]));
    __syncthreads();

    // sum
    float sum = 0.f;
    for (int j = tid; j < n; j += 128) sum += expf(base[j] - m);
#pragma unroll
    for (int off = 16; off; off >>= 1)
        sum += __shfl_xor_sync(0xffffffffu, sum, off);
    if (lane == 0) red[w] = sum;
    __syncthreads();
    const float inv = 1.f / (red[0] + red[1] + red[2] + red[3]);

    // write probabilities
    for (int j = tid; j < n; j += 128) base[j] = expf(base[j] - m) * inv;

    // zero tail within the diagonal 64-tile
    const int te = ((i >> 6) + 1) << 6;
    for (int j = n + tid; j < te; j += 128) base[j] = 0.f;
}

// =============================================================
// Phase 3: y = P @ V. One block per (qb, h). 256 threads.
// thread: row r = tid>>2, cols cg..cg+31 where cg = (tid&3)*32.
// smem: Ps[64][65], Vs[64][128]
// =============================================================
#define PV_SMEM ((64 * 65 + 64 * 128) * 4)

__global__ void __launch_bounds__(256)
pv_kernel()
{
    const int qb = blockIdx.x;
    const int h  = blockIdx.y;

    extern __shared__ float sm[];
    float* Ps = sm;              // [64][65]
    float* Vs = sm + 64 * 65;    // [64][128]

    const int tid = threadIdx.x;
    const int r  = tid >> 2;
    const int cg = (tid & 3) * 32;

    float4 o[8];
#pragma unroll
    for (int u = 0; u < 8; u++) o[u] = make_float4(0.f, 0.f, 0.f, 0.f);

    const float* Pg = g_s + ((size_t)h * S_LEN + (size_t)qb * 64) * S_LEN;

    for (int kb = 0; kb <= qb; kb++) {
#pragma unroll
        for (int i = 0; i < 4; i++) {
            int idx = tid + i * 256;      // 0..1023 = 64 rows x 16 cgroups
            int row = idx >> 4;
            int c4  = (idx & 15) * 4;
            float4 p4 = *(const float4*)(Pg + (size_t)row * S_LEN + kb * 64 + c4);
            Ps[row * 65 + c4 + 0] = p4.x;
            Ps[row * 65 + c4 + 1] = p4.y;
            Ps[row * 65 + c4 + 2] = p4.z;
            Ps[row * 65 + c4 + 3] = p4.w;
        }
        const float* Vg = g_v + (size_t)(kb * 64) * KVD + (h >> 2) * HD;
#pragma unroll
        for (int i = 0; i < 8; i++) {
            int idx = tid + i * 256;      // 64 rows x 32 kgroups
            int row = idx >> 5;
            int kg  = idx & 31;
            *(float4*)(Vs + row * 128 + kg * 4) =
                *(const float4*)(Vg + (size_t)row * KVD + kg * 4);
        }
        __syncthreads();

#pragma unroll 2
        for (int j = 0; j < 64; j++) {
            float p = Ps[r * 65 + j];
            const float4* v4 = (const float4*)(Vs + j * 128 + cg);
#pragma unroll
            for (int u = 0; u < 8; u++) {
                float4 vv = v4[u];
                o[u].x += p * vv.x;
                o[u].y += p * vv.y;
                o[u].z += p * vv.z;
                o[u].w += p * vv.w;
            }
        }
        __syncthreads();
    }

    float* Y = g_y + (size_t)(qb * 64 + r) * DMODEL + h * HD + cg;
#pragma unroll
    for (int u = 0; u < 8; u++)
        *(float4*)(Y + 4 * u) = o[u];
}

// =============================================================
// v-direction rejection, in place on g_y. One warp per (s, h).
// =============================================================
__global__ void reject_kernel()
{
    const int w    = blockIdx.x * (blockDim.x >> 5) + (threadIdx.x >> 5);
    const int lane = threadIdx.x & 31;
    const int s = w >> 4;          // w in [0, S*16)
    const int h = w & 15;
    if (s >= S_LEN) return;

    const int kv = h >> 2;
    float* yp = g_y + (size_t)s * DMODEL + h * HD;
    const float* vp = g_v + (size_t)s * KVD + kv * HD;

    float4 vv = *(const float4*)(vp + lane * 4);
    float4 yy = *(const float4*)(yp + lane * 4);
    float vsq = vv.x * vv.x + vv.y * vv.y + vv.z * vv.z + vv.w * vv.w;
    float yv  = yy.x * vv.x + yy.y * vv.y + yy.z * vv.z + yy.w * vv.w;
#pragma unroll
    for (int off = 16; off; off >>= 1) {
        vsq += __shfl_xor_sync(0xffffffffu, vsq, off);
        yv  += __shfl_xor_sync(0xffffffffu, yv, off);
    }
    float mx = fmaxf(sqrtf(vsq), 1e-12f);
    float c2 = yv / (mx * mx);
    yy.x -= c2 * vv.x; yy.y -= c2 * vv.y;
    yy.z -= c2 * vv.z; yy.w -= c2 * vv.w;
    *(float4*)(yp + lane * 4) = yy;
}

// =============================================================
// v output transpose: [S][KV*128] -> [KV][S][128]
// =============================================================
__global__ void v_transpose_kernel(const float* __restrict__ v, float* __restrict__ out)
{
    int idx = blockIdx.x * blockDim.x + threadIdx.x;
    if (idx < S_LEN * KVD / 4) {
        int f = idx * 4;
        int s = f / KVD;
        int rem = f % KVD;
        int kvh = rem / HD;
        int d = rem % HD;
        float4 val = *(const float4*)(v + f);
        *(float4*)(out + (size_t)kvh * S_LEN * HD + (size_t)s * HD + d) = val;
    }
}

// =============================================================
// launch — input identification by size signature (see R2 notes).
// =============================================================
extern "C" void kernel_launch(void* const* d_in, const int* in_sizes, int n_in,
                              void* d_out, int out_size)
{
    int big[3], nbig = 0;
    int med[2], nmed = 0;
    int gidx = -1;
    for (int i = 0; i < n_in && i < 6; i++) {
        int sz = in_sizes[i];
        if (sz == NHEADS)                 gidx = i;
        else if (sz == S_LEN * KVD)       { if (nmed < 2) med[nmed++] = i; }
        else                              { if (nbig < 3) big[nbig++] = i; }
    }
    int ix, iwq, iwk, iwv, iwp, ig;
    ig  = (gidx >= 0) ? gidx : 5;
    iwk = (nmed > 0) ? med[0] : 2;
    iwv = (nmed > 1) ? med[1] : 3;
    if (ig == 5) {          // dict / signature order: x, Wq, ..., Wp
        ix  = (nbig > 0) ? big[0] : 0;
        iwq = (nbig > 1) ? big[1] : 1;
        iwp = (nbig > 2) ? big[2] : 4;
    } else {                // alphabetical: Wk, Wp, Wq, Wv, q_gain, x
        iwp = (nbig > 0) ? big[0] : 1;
        iwq = (nbig > 1) ? big[1] : 2;
        ix  = (nbig > 2) ? big[2] : 5;
    }

    const float* x  = (const float*)d_in[ix];
    const float* Wq = (const float*)d_in[iwq];
    const float* Wk = (const float*)d_in[iwk];
    const float* Wv = (const float*)d_in[iwv];
    const float* Wp = (const float*)d_in[iwp];
    const float* qg = (const float*)d_in[ig];
    float* out = (float*)d_out;

    float *pq, *pk, *pv, *py;
    cudaGetSymbolAddress((void**)&pq, g_q);
    cudaGetSymbolAddress((void**)&pk, g_k);
    cudaGetSymbolAddress((void**)&pv, g_v);
    cudaGetSymbolAddress((void**)&py, g_y);

    cudaFuncSetAttribute(score_kernel, cudaFuncAttributeMaxDynamicSharedMemorySize, SCORE_SMEM);
    cudaFuncSetAttribute(pv_kernel,    cudaFuncAttributeMaxDynamicSharedMemorySize, PV_SMEM);

    // projections
    gemm_nt_kernel<<<dim3(DMODEL / 128, S_LEN / 128), 256>>>(x, Wq, pq, S_LEN, DMODEL, DMODEL);
    gemm_nt_kernel<<<dim3(KVD / 128,    S_LEN / 128), 256>>>(x, Wk, pk, S_LEN, KVD,    DMODEL);
    gemm_nt_kernel<<<dim3(KVD / 128,    S_LEN / 128), 256>>>(x, Wv, pv, S_LEN, KVD,    DMODEL);

    // rmsnorm + rope (+ gain on q): one warp per (s, head)
    rope2_kernel<<<(S_LEN * NHEADS) / 4, 128>>>(pq, DMODEL, NHEADS, qg);
    rope2_kernel<<<(S_LEN * KVH)    / 4, 128>>>(pk, KVD,    KVH,    nullptr);

    // attention: scores -> softmax -> P@V
    score_kernel<<<dim3(S_LEN / 64, S_LEN / 64, NHEADS), 256, SCORE_SMEM>>>();
    softmax_kernel<<<dim3(S_LEN, NHEADS), 128>>>();
    pv_kernel<<<dim3(S_LEN / 64, NHEADS), 256, PV_SMEM>>>();

    // v-rejection (in place on g_y)
    reject_kernel<<<(S_LEN * NHEADS) / 4, 128>>>();

    // output projection
    gemm_nt_kernel<<<dim3(DMODEL / 128, S_LEN / 128), 256>>>(py, Wp, out, S_LEN, DMODEL, DMODEL);

    // v second output
    if (out_size >= S_LEN * DMODEL + S_LEN * KVD)
        v_transpose_kernel<<<(S_LEN * KVD / 4 + 255) / 256, 256>>>(pv, out + (size_t)S_LEN * DMODEL);
}

// round 4
// speedup vs baseline: 2.2934x; 2.2934x over previous
#include <cuda_runtime.h>
#include <cuda_bf16.h>
#include <math.h>
#include <stdint.h>

// Problem constants (B=1)
#define S_LEN  2048
#define DMODEL 2048
#define NHEADS 16
#define HD     128
#define KVH    4
#define KVD    512   // KVH*HD

// ---------------- scratch (no allocations allowed) ----------------
__device__ float g_q[S_LEN * DMODEL];            // q proj -> normed+roped in place
__device__ float g_k[S_LEN * KVD];               // k proj -> normed+roped in place
__device__ float g_v[S_LEN * KVD];               // v proj
__device__ float g_y[S_LEN * DMODEL];            // attention output
__device__ float g_s[(size_t)NHEADS * S_LEN * S_LEN];  // scores / probs (268 MB)

// =============================================================
// tf32 split MMA helpers
// =============================================================
__device__ __forceinline__ uint32_t f2tf32(float v) {
    uint32_t r;
    asm volatile("cvt.rna.tf32.f32 %0, %1;" : "=r"(r) : "f"(v));
    return r;
}

__device__ __forceinline__ void mma_tf32(float* c, const uint32_t* a, const uint32_t* b) {
    asm volatile(
        "mma.sync.aligned.m16n8k8.row.col.f32.tf32.tf32.f32 "
        "{%0,%1,%2,%3}, {%4,%5,%6,%7}, {%8,%9}, {%0,%1,%2,%3};\n"
        : "+f"(c[0]), "+f"(c[1]), "+f"(c[2]), "+f"(c[3])
        : "r"(a[0]), "r"(a[1]), "r"(a[2]), "r"(a[3]),
          "r"(b[0]), "r"(b[1]));
}

// =============================================================
// Generic batched GEMM, tf32 3-pass split (fp32-accurate):
//   C[z] = alpha * A[z] * op(B[z])
// A: row-major [M,K], op(B): NT mode -> B row-major [N,K] (B^T used),
//                     NN mode -> B row-major [K,N].
// Per-z offsets: A += z*astride, B += (z>>bshift)*bstride, C += z*cstride.
// mode bits: 1 = NN B-layout, 2 = causal tile skip (bn>bm), 4 = triangular
// K-limit (kmax = (bm+1)*128).
// Block tile 128x128xBK16, 256 threads, 8 warps (2 M x 4 N), warp 64x32.
// Smem layout per operand: [row][20] where the 16 k-values are stored as two
// 8-col groups with (k, k+4) adjacent: col = (k>>3)*8 + (k&3)*2 + ((k>>2)&1).
// =============================================================
#define GSTRIDE 20

__global__ void __launch_bounds__(256)
gemm_tf32_kernel(const float* __restrict__ A, const float* __restrict__ B,
                 float* __restrict__ C, int M, int N, int K,
                 int lda, int ldb, int ldc,
                 size_t astride, size_t bstride, size_t cstride, int bshift,
                 float alpha, int mode)
{
    const int bm = blockIdx.y, bn = blockIdx.x, z = blockIdx.z;
    if ((mode & 2) && bn > bm) return;

    __shared__ __align__(16) uint32_t AsH[128 * GSTRIDE];
    __shared__ __align__(16) uint32_t AsL[128 * GSTRIDE];
    __shared__ __align__(16) uint32_t BsH[128 * GSTRIDE];
    __shared__ __align__(16) uint32_t BsL[128 * GSTRIDE];

    const int tid  = threadIdx.x;
    const int lane = tid & 31;
    const int wid  = tid >> 5;
    const int wm   = (wid >> 2) * 64;   // warp M offset (0 or 64)
    const int wn   = (wid & 3) * 32;    // warp N offset
    const int g8   = lane >> 2;         // groupID 0..7
    const int tig  = lane & 3;          // thread in group 0..3

    const float* Ab = A + z * astride + (size_t)bm * 128 * lda;
    const float* Bb;
    if (mode & 1) Bb = B + (size_t)(z >> bshift) * bstride + bn * 128;          // NN: col offset
    else          Bb = B + (size_t)(z >> bshift) * bstride + (size_t)bn * 128 * ldb; // NT: row offset

    const int kmax = (mode & 4) ? min(K, (bm + 1) * 128) : K;

    float acc[4][4][4];
#pragma unroll
    for (int mf = 0; mf < 4; mf++)
#pragma unroll
        for (int nf = 0; nf < 4; nf++)
#pragma unroll
            for (int r = 0; r < 4; r++) acc[mf][nf][r] = 0.f;

    for (int k0 = 0; k0 < kmax; k0 += 16) {
        // ---- load A tile 128x16 ----
#pragma unroll
        for (int i = 0; i < 2; i++) {
            int idx = tid + i * 256;           // 0..511
            int row = idx >> 2;
            int c   = idx & 3;                 // k-group of 4
            float4 v = *(const float4*)(Ab + (size_t)row * lda + k0 + c * 4);
            float vv[4] = {v.x, v.y, v.z, v.w};
#pragma unroll
            for (int e = 0; e < 4; e++) {
                int k = c * 4 + e;
                int col = (k >> 3) * 8 + (k & 3) * 2 + ((k >> 2) & 1);
                uint32_t hi = f2tf32(vv[e]);
                float lo = vv[e] - __uint_as_float(hi);
                AsH[row * GSTRIDE + col] = hi;
                AsL[row * GSTRIDE + col] = f2tf32(lo);
            }
        }
        // ---- load B tile ----
        if (mode & 1) {
            // NN: B[K,N]; tile 16(k) x 128(n)
#pragma unroll
            for (int i = 0; i < 2; i++) {
                int idx = tid + i * 256;       // 0..511 = 16 krows x 32 ncols4
                int kr = idx >> 5;
                int nc = idx & 31;
                float4 v = *(const float4*)(Bb + (size_t)(k0 + kr) * ldb + nc * 4);
                int col = (kr >> 3) * 8 + (kr & 3) * 2 + ((kr >> 2) & 1);
                float vv[4] = {v.x, v.y, v.z, v.w};
#pragma unroll
                for (int e = 0; e < 4; e++) {
                    int n = nc * 4 + e;
                    uint32_t hi = f2tf32(vv[e]);
                    float lo = vv[e] - __uint_as_float(hi);
                    BsH[n * GSTRIDE + col] = hi;
                    BsL[n * GSTRIDE + col] = f2tf32(lo);
                }
            }
        } else {
            // NT: B[N,K]; tile 128(n) x 16(k)
#pragma unroll
            for (int i = 0; i < 2; i++) {
                int idx = tid + i * 256;
                int row = idx >> 2;
                int c   = idx & 3;
                float4 v = *(const float4*)(Bb + (size_t)row * ldb + k0 + c * 4);
                float vv[4] = {v.x, v.y, v.z, v.w};
#pragma unroll
                for (int e = 0; e < 4; e++) {
                    int k = c * 4 + e;
                    int col = (k >> 3) * 8 + (k & 3) * 2 + ((k >> 2) & 1);
                    uint32_t hi = f2tf32(vv[e]);
                    float lo = vv[e] - __uint_as_float(hi);
                    BsH[row * GSTRIDE + col] = hi;
                    BsL[row * GSTRIDE + col] = f2tf32(lo);
                }
            }
        }
        __syncthreads();

        // ---- compute: two k8 groups ----
#pragma unroll
        for (int g = 0; g < 2; g++) {
            uint32_t aH[4][4], aL[4][4], bH[4][2], bL[4][2];
#pragma unroll
            for (int mf = 0; mf < 4; mf++) {
                int row0 = wm + mf * 16 + g8;
                int row1 = row0 + 8;
                int off  = g * 8 + tig * 2;
                uint2 h0 = *(const uint2*)&AsH[row0 * GSTRIDE + off];
                uint2 h1 = *(const uint2*)&AsH[row1 * GSTRIDE + off];
                uint2 l0 = *(const uint2*)&AsL[row0 * GSTRIDE + off];
                uint2 l1 = *(const uint2*)&AsL[row1 * GSTRIDE + off];
                aH[mf][0] = h0.x; aH[mf][1] = h1.x; aH[mf][2] = h0.y; aH[mf][3] = h1.y;
                aL[mf][0] = l0.x; aL[mf][1] = l1.x; aL[mf][2] = l0.y; aL[mf][3] = l1.y;
            }
#pragma unroll
            for (int nf = 0; nf < 4; nf++) {
                int n   = wn + nf * 8 + g8;
                int off = g * 8 + tig * 2;
                uint2 h = *(const uint2*)&BsH[n * GSTRIDE + off];
                uint2 l = *(const uint2*)&BsL[n * GSTRIDE + off];
                bH[nf][0] = h.x; bH[nf][1] = h.y;
                bL[nf][0] = l.x; bL[nf][1] = l.y;
            }
#pragma unroll
            for (int mf = 0; mf < 4; mf++)
#pragma unroll
                for (int nf = 0; nf < 4; nf++) {
                    mma_tf32(acc[mf][nf], aH[mf], bH[nf]);
                    mma_tf32(acc[mf][nf], aH[mf], bL[nf]);
                    mma_tf32(acc[mf][nf], aL[mf], bH[nf]);
                }
        }
        __syncthreads();
    }

    // ---- epilogue ----
    float* Cb = C + z * cstride + (size_t)bm * 128 * ldc + bn * 128;
#pragma unroll
    for (int mf = 0; mf < 4; mf++) {
        int row0 = wm + mf * 16 + g8;
        int row1 = row0 + 8;
#pragma unroll
        for (int nf = 0; nf < 4; nf++) {
            int col = wn + nf * 8 + tig * 2;
            float* p0 = Cb + (size_t)row0 * ldc + col;
            float* p1 = Cb + (size_t)row1 * ldc + col;
            *(float2*)p0 = make_float2(acc[mf][nf][0] * alpha, acc[mf][nf][1] * alpha);
            *(float2*)p1 = make_float2(acc[mf][nf][2] * alpha, acc[mf][nf][3] * alpha);
        }
    }
}

// =============================================================
// RMSNorm + RoPE: ONE WARP per (s, head). Pure warp shuffles.
// =============================================================
__global__ void rope2_kernel(float* __restrict__ buf, int rowstride, int nheads,
                             const float* __restrict__ gain)
{
    const int w    = blockIdx.x * (blockDim.x >> 5) + (threadIdx.x >> 5);
    const int lane = threadIdx.x & 31;
    const int s = w / nheads;
    const int h = w % nheads;
    if (s >= S_LEN) return;

    float* p = buf + (size_t)s * rowstride + h * HD;

    float2 u1 = *(const float2*)(p + 2 * lane);
    float2 u2 = *(const float2*)(p + 64 + 2 * lane);

    float ss = u1.x * u1.x + u1.y * u1.y + u2.x * u2.x + u2.y * u2.y;
#pragma unroll
    for (int off = 16; off; off >>= 1)
        ss += __shfl_xor_sync(0xffffffffu, ss, off);

    const float r = rsqrtf(ss * (1.f / 128.f) + 1.1920929e-07f);
    const float g = gain ? gain[h] : 1.0f;

    float x1a = u1.x * r, x1b = u1.y * r;
    float x2a = u2.x * r, x2b = u2.y * r;

    const float kln = 9.210340371976184f / 128.f;   // ln(10000)/128
    float th0 = (float)s * expf(-(float)(2 * (2 * lane))     * kln);
    float th1 = (float)s * expf(-(float)(2 * (2 * lane + 1)) * kln);
    float c0, s0, c1, s1;
    sincosf(th0, &s0, &c0);
    sincosf(th1, &s1, &c1);

    float o1a = x1a * c0 + x2a * s0;
    float o1b = x1b * c1 + x2b * s1;
    float o2a = x2a * c0 - x1a * s0;
    float o2b = x2b * c1 - x1b * s1;

    *(float2*)(p + 2 * lane)      = make_float2(o1a * g, o1b * g);
    *(float2*)(p + 64 + 2 * lane) = make_float2(o2a * g, o2b * g);
}

// =============================================================
// Softmax per (row i, head h) over j in [0, i]; zero tail out to
// the row's 128-tile boundary so PV's triangular K-limit is safe.
// =============================================================
__global__ void __launch_bounds__(128)
softmax_kernel()
{
    const int i = blockIdx.x;
    const int h = blockIdx.y;
    float* base = g_s + ((size_t)h * S_LEN + i) * S_LEN;
    const int n = i + 1;

    const int tid = threadIdx.x;
    const int lane = tid & 31, w = tid >> 5;
    __shared__ float red[4];

    float m = -INFINITY;
    for (int j = tid; j < n; j += 128) m = fmaxf(m, base[j]);
#pragma unroll
    for (int off = 16; off; off >>= 1)
        m = fmaxf(m, __shfl_xor_sync(0xffffffffu, m, off));
    if (lane == 0) red[w] = m;
    __syncthreads();
    m = fmaxf(fmaxf(red[0], red[1]), fmaxf(red[2], red[3]));
    __syncthreads();

    float sum = 0.f;
    for (int j = tid; j < n; j += 128) sum += expf(base[j] - m);
#pragma unroll
    for (int off = 16; off; off >>= 1)
        sum += __shfl_xor_sync(0xffffffffu, sum, off);
    if (lane == 0) red[w] = sum;
    __syncthreads();
    const float inv = 1.f / (red[0] + red[1] + red[2] + red[3]);

    for (int j = tid; j < n; j += 128) base[j] = expf(base[j] - m) * inv;

    // zero tail out to the 128-tile boundary (PV reads k < (bm+1)*128)
    const int te = ((i >> 7) + 1) << 7;
    for (int j = n + tid; j < te; j += 128) base[j] = 0.f;
}

// =============================================================
// v-direction rejection, in place on g_y. One warp per (s, h).
// =============================================================
__global__ void reject_kernel()
{
    const int w    = blockIdx.x * (blockDim.x >> 5) + (threadIdx.x >> 5);
    const int lane = threadIdx.x & 31;
    const int s = w >> 4;
    const int h = w & 15;
    if (s >= S_LEN) return;

    const int kv = h >> 2;
    float* yp = g_y + (size_t)s * DMODEL + h * HD;
    const float* vp = g_v + (size_t)s * KVD + kv * HD;

    float4 vv = *(const float4*)(vp + lane * 4);
    float4 yy = *(const float4*)(yp + lane * 4);
    float vsq = vv.x * vv.x + vv.y * vv.y + vv.z * vv.z + vv.w * vv.w;
    float yv  = yy.x * vv.x + yy.y * vv.y + yy.z * vv.z + yy.w * vv.w;
#pragma unroll
    for (int off = 16; off; off >>= 1) {
        vsq += __shfl_xor_sync(0xffffffffu, vsq, off);
        yv  += __shfl_xor_sync(0xffffffffu, yv, off);
    }
    float mx = fmaxf(sqrtf(vsq), 1e-12f);
    float c2 = yv / (mx * mx);
    yy.x -= c2 * vv.x; yy.y -= c2 * vv.y;
    yy.z -= c2 * vv.z; yy.w -= c2 * vv.w;
    *(float4*)(yp + lane * 4) = yy;
}

// =============================================================
// v output transpose: [S][KV*128] -> [KV][S][128]
// =============================================================
__global__ void v_transpose_kernel(const float* __restrict__ v, float* __restrict__ out)
{
    int idx = blockIdx.x * blockDim.x + threadIdx.x;
    if (idx < S_LEN * KVD / 4) {
        int f = idx * 4;
        int s = f / KVD;
        int rem = f % KVD;
        int kvh = rem / HD;
        int d = rem % HD;
        float4 val = *(const float4*)(v + f);
        *(float4*)(out + (size_t)kvh * S_LEN * HD + (size_t)s * HD + d) = val;
    }
}

// =============================================================
// launch — input identification by size signature (see R2 notes).
// =============================================================
extern "C" void kernel_launch(void* const* d_in, const int* in_sizes, int n_in,
                              void* d_out, int out_size)
{
    int big[3], nbig = 0;
    int med[2], nmed = 0;
    int gidx = -1;
    for (int i = 0; i < n_in && i < 6; i++) {
        int sz = in_sizes[i];
        if (sz == NHEADS)                 gidx = i;
        else if (sz == S_LEN * KVD)       { if (nmed < 2) med[nmed++] = i; }
        else                              { if (nbig < 3) big[nbig++] = i; }
    }
    int ix, iwq, iwk, iwv, iwp, ig;
    ig  = (gidx >= 0) ? gidx : 5;
    iwk = (nmed > 0) ? med[0] : 2;
    iwv = (nmed > 1) ? med[1] : 3;
    if (ig == 5) {          // dict / signature order: x, Wq, ..., Wp
        ix  = (nbig > 0) ? big[0] : 0;
        iwq = (nbig > 1) ? big[1] : 1;
        iwp = (nbig > 2) ? big[2] : 4;
    } else {                // alphabetical: Wk, Wp, Wq, Wv, q_gain, x
        iwp = (nbig > 0) ? big[0] : 1;
        iwq = (nbig > 1) ? big[1] : 2;
        ix  = (nbig > 2) ? big[2] : 5;
    }

    const float* x  = (const float*)d_in[ix];
    const float* Wq = (const float*)d_in[iwq];
    const float* Wk = (const float*)d_in[iwk];
    const float* Wv = (const float*)d_in[iwv];
    const float* Wp = (const float*)d_in[iwp];
    const float* qg = (const float*)d_in[ig];
    float* out = (float*)d_out;

    float *pq, *pk, *pv, *py, *ps;
    cudaGetSymbolAddress((void**)&pq, g_q);
    cudaGetSymbolAddress((void**)&pk, g_k);
    cudaGetSymbolAddress((void**)&pv, g_v);
    cudaGetSymbolAddress((void**)&py, g_y);
    cudaGetSymbolAddress((void**)&ps, g_s);

    const float scale = 0.08838834764831845f;   // 1/sqrt(128)

    // projections (NT): C = A * W^T
    gemm_tf32_kernel<<<dim3(DMODEL / 128, S_LEN / 128, 1), 256>>>(
        x, Wq, pq, S_LEN, DMODEL, DMODEL, DMODEL, DMODEL, DMODEL,
        0, 0, 0, 0, 1.0f, 0);
    gemm_tf32_kernel<<<dim3(KVD / 128, S_LEN / 128, 1), 256>>>(
        x, Wk, pk, S_LEN, KVD, DMODEL, DMODEL, DMODEL, KVD,
        0, 0, 0, 0, 1.0f, 0);
    gemm_tf32_kernel<<<dim3(KVD / 128, S_LEN / 128, 1), 256>>>(
        x, Wv, pv, S_LEN, KVD, DMODEL, DMODEL, DMODEL, KVD,
        0, 0, 0, 0, 1.0f, 0);

    // rmsnorm + rope (+ gain on q)
    rope2_kernel<<<(S_LEN * NHEADS) / 4, 128>>>(pq, DMODEL, NHEADS, qg);
    rope2_kernel<<<(S_LEN * KVH)    / 4, 128>>>(pk, KVD,    KVH,    nullptr);

    // scores (NT, batched over 16 heads, causal tile skip):
    //   S[h] = scale * Q[:, h*128:...] @ K[:, (h>>2)*128:...]^T
    gemm_tf32_kernel<<<dim3(S_LEN / 128, S_LEN / 128, NHEADS), 256>>>(
        pq, pk, ps, S_LEN, S_LEN, HD, DMODEL, KVD, S_LEN,
        (size_t)HD, (size_t)HD, (size_t)S_LEN * S_LEN, 2, scale, 2);

    // softmax (causal rows)
    softmax_kernel<<<dim3(S_LEN, NHEADS), 128>>>();

    // PV (NN, batched, triangular K-limit): Y[:, h*128:] = P[h] @ V[:, (h>>2)*128:]
    gemm_tf32_kernel<<<dim3(HD / 128, S_LEN / 128, NHEADS), 256>>>(
        ps, pv, py, S_LEN, HD, S_LEN, S_LEN, KVD, DMODEL,
        (size_t)S_LEN * S_LEN, (size_t)HD, (size_t)HD, 2, 1.0f, 1 | 4);

    // v-rejection (in place on g_y)
    reject_kernel<<<(S_LEN * NHEADS) / 4, 128>>>();

    // output projection (NT)
    gemm_tf32_kernel<<<dim3(DMODEL / 128, S_LEN / 128, 1), 256>>>(
        py, Wp, out, S_LEN, DMODEL, DMODEL, DMODEL, DMODEL, DMODEL,
        0, 0, 0, 0, 1.0f, 0);

    // v second output
    if (out_size >= S_LEN * DMODEL + S_LEN * KVD)
        v_transpose_kernel<<<(S_LEN * KVD / 4 + 255) / 256, 256>>>(pv, out + (size_t)S_LEN * DMODEL);
}

// round 6
// speedup vs baseline: 3.5974x; 1.5686x over previous
#include <cuda_runtime.h>
#include <cuda_bf16.h>
#include <math.h>
#include <stdint.h>

// Problem constants (B=1)
#define S_LEN  2048
#define DMODEL 2048
#define NHEADS 16
#define HD     128
#define KVH    4
#define KVD    512   // KVH*HD

// ---------------- scratch (no allocations allowed) ----------------
__device__ float g_q[S_LEN * DMODEL];            // q proj -> normed+roped in place
__device__ float g_k[S_LEN * KVD];               // k proj -> normed+roped in place
__device__ float g_v[S_LEN * KVD];               // v proj
__device__ float g_y[S_LEN * DMODEL];            // attention output
__device__ float g_s[(size_t)NHEADS * S_LEN * S_LEN];  // scores / probs (268 MB)

// =============================================================
// bf16 split helpers
// =============================================================
__device__ __forceinline__ void mma_bf16(float* c, const uint32_t* a, const uint32_t* b) {
    asm volatile(
        "mma.sync.aligned.m16n8k16.row.col.f32.bf16.bf16.f32 "
        "{%0,%1,%2,%3}, {%4,%5,%6,%7}, {%8,%9}, {%0,%1,%2,%3};\n"
        : "+f"(c[0]), "+f"(c[1]), "+f"(c[2]), "+f"(c[3])
        : "r"(a[0]), "r"(a[1]), "r"(a[2]), "r"(a[3]),
          "r"(b[0]), "r"(b[1]));
}

// convert a float pair (x = lower-k, y = higher-k) into packed bf16x2 hi & lo
__device__ __forceinline__ void cvtpair(float x, float y, uint32_t& hi, uint32_t& lo) {
    __nv_bfloat16 hx = __float2bfloat16_rn(x);
    __nv_bfloat16 hy = __float2bfloat16_rn(y);
    float rx = x - __bfloat162float(hx);
    float ry = y - __bfloat162float(hy);
    __nv_bfloat16 lx = __float2bfloat16_rn(rx);
    __nv_bfloat16 ly = __float2bfloat16_rn(ry);
    hi = (uint32_t)__bfloat16_as_ushort(hx) | ((uint32_t)__bfloat16_as_ushort(hy) << 16);
    lo = (uint32_t)__bfloat16_as_ushort(lx) | ((uint32_t)__bfloat16_as_ushort(ly) << 16);
}

// =============================================================
// Generic batched GEMM, bf16 3-pass split (fp32-accurate ~3e-5):
//   C[z] = alpha * A[z] * op(B[z])
// A row-major [M,K]; NT mode: B row-major [N,K] (uses B^T);
//                    NN mode: B row-major [K,N].
// mode bits: 1 = NN, 2 = causal tile skip (bn>bm), 4 = triangular
// K-limit (kmax = (bm+1)*128).
// Block 128x128xBK32, 256 threads, 8 warps (2Mx4N), warp tile 64x32.
// Smem (per stage, per operand): rows of 48 u32; for k-pair c (= k>>1),
// group [hi_c, hi_{c+4}, lo_c, lo_{c+4}] is one aligned 16B quad at
//   row*48 + (c>>3)*16 + (c&3)*4   (+0 hi / +2 lo, +1 for the c+4 member)
// so every mma fragment is one LDS.128. 2-stage double buffer,
// register-staged global loads.
// =============================================================
#define SST 48
#define GSMEM_BYTES (2 * 2 * 128 * SST * 4)   // 98304

__global__ void __launch_bounds__(256)
gemm_bf16x3_kernel(const float* __restrict__ A, const float* __restrict__ B,
                   float* __restrict__ C, int M, int N, int K,
                   int lda, int ldb, int ldc,
                   size_t astride, size_t bstride, size_t cstride, int bshift,
                   float alpha, int mode)
{
    const int bm = blockIdx.y, bn = blockIdx.x, z = blockIdx.z;
    if ((mode & 2) && bn > bm) return;

    extern __shared__ uint32_t smu[];
    uint32_t* AsBase = smu;                     // [2][128][SST]
    uint32_t* BsBase = smu + 2 * 128 * SST;     // [2][128][SST]

    const int tid  = threadIdx.x;
    const int lane = tid & 31;
    const int wid  = tid >> 5;
    const int wm   = (wid >> 2) * 64;
    const int wn   = (wid & 3) * 32;
    const int g8   = lane >> 2;
    const int tig  = lane & 3;

    const float* Ab = A + z * astride + (size_t)bm * 128 * lda;
    const float* Bb = (mode & 1)
        ? B + (size_t)(z >> bshift) * bstride + bn * 128
        : B + (size_t)(z >> bshift) * bstride + (size_t)bn * 128 * ldb;

    const int kmax  = (mode & 4) ? min(K, (bm + 1) * 128) : K;
    const int nIter = kmax >> 5;

    float acc[4][4][4] = {};
    float4 ar[4], br[4];

    // ---- register-staged global loads ----
    auto loadAB = [&](int k0) {
#pragma unroll
        for (int i = 0; i < 4; i++) {
            int idx = tid + i * 256;        // 0..1023 = 128 rows x 8 float4
            int row = idx >> 3, j = idx & 7;
            ar[i] = *(const float4*)(Ab + (size_t)row * lda + k0 + j * 4);
        }
        if (mode & 1) {
#pragma unroll
            for (int i = 0; i < 2; i++) {
                int task = tid + i * 256;   // 0..511 = 16 pair-rows x 32 ncol4
                int pr = task >> 5, nc = task & 31;
                br[2 * i]     = *(const float4*)(Bb + (size_t)(k0 + 2 * pr)     * ldb + nc * 4);
                br[2 * i + 1] = *(const float4*)(Bb + (size_t)(k0 + 2 * pr + 1) * ldb + nc * 4);
            }
        } else {
#pragma unroll
            for (int i = 0; i < 4; i++) {
                int idx = tid + i * 256;
                int row = idx >> 3, j = idx & 7;
                br[i] = *(const float4*)(Bb + (size_t)row * ldb + k0 + j * 4);
            }
        }
    };

    auto stpair = [&](uint32_t* base, int row, int c, uint32_t hi, uint32_t lo) {
        int ks = c >> 3, cc = c & 7, s = cc & 3, h = cc >> 2;
        uint32_t* p = base + row * SST + ks * 16 + s * 4 + h;
        p[0] = hi; p[2] = lo;
    };

    auto storeAB = [&](int st) {
        uint32_t* As = AsBase + st * 128 * SST;
        uint32_t* Bs = BsBase + st * 128 * SST;
#pragma unroll
        for (int i = 0; i < 4; i++) {
            int idx = tid + i * 256, row = idx >> 3, j = idx & 7;
            uint32_t hi, lo;
            cvtpair(ar[i].x, ar[i].y, hi, lo); stpair(As, row, 2 * j,     hi, lo);
            cvtpair(ar[i].z, ar[i].w, hi, lo); stpair(As, row, 2 * j + 1, hi, lo);
        }
        if (mode & 1) {
#pragma unroll
            for (int i = 0; i < 2; i++) {
                int task = tid + i * 256, pr = task >> 5, nc = task & 31;
                float e0[4] = {br[2*i].x,   br[2*i].y,   br[2*i].z,   br[2*i].w};
                float e1[4] = {br[2*i+1].x, br[2*i+1].y, br[2*i+1].z, br[2*i+1].w};
#pragma unroll
                for (int e = 0; e < 4; e++) {
                    uint32_t hi, lo;
                    cvtpair(e0[e], e1[e], hi, lo);       // low half = lower k
                    stpair(Bs, nc * 4 + e, pr, hi, lo);
                }
            }
        } else {
#pragma unroll
            for (int i = 0; i < 4; i++) {
                int idx = tid + i * 256, row = idx >> 3, j = idx & 7;
                uint32_t hi, lo;
                cvtpair(br[i].x, br[i].y, hi, lo); stpair(Bs, row, 2 * j,     hi, lo);
                cvtpair(br[i].z, br[i].w, hi, lo); stpair(Bs, row, 2 * j + 1, hi, lo);
            }
        }
    };

    auto compute = [&](int st) {
        const uint32_t* As = AsBase + st * 128 * SST;
        const uint32_t* Bs = BsBase + st * 128 * SST;
#pragma unroll
        for (int g = 0; g < 2; g++) {           // two k16 steps
            uint32_t aH[4][4], aL[4][4], bH[4][2], bL[4][2];
#pragma unroll
            for (int mf = 0; mf < 4; mf++) {
                int r0 = wm + mf * 16 + g8;
                uint4 q0 = *(const uint4*)(As + r0 * SST + g * 16 + tig * 4);
                uint4 q1 = *(const uint4*)(As + (r0 + 8) * SST + g * 16 + tig * 4);
                aH[mf][0] = q0.x; aH[mf][1] = q1.x; aH[mf][2] = q0.y; aH[mf][3] = q1.y;
                aL[mf][0] = q0.z; aL[mf][1] = q1.z; aL[mf][2] = q0.w; aL[mf][3] = q1.w;
            }
#pragma unroll
            for (int nf = 0; nf < 4; nf++) {
                int n = wn + nf * 8 + g8;
                uint4 q = *(const uint4*)(Bs + n * SST + g * 16 + tig * 4);
                bH[nf][0] = q.x; bH[nf][1] = q.y;
                bL[nf][0] = q.z; bL[nf][1] = q.w;
            }
#pragma unroll
            for (int mf = 0; mf < 4; mf++)
#pragma unroll
                for (int nf = 0; nf < 4; nf++) {
                    mma_bf16(acc[mf][nf], aL[mf], bH[nf]);
                    mma_bf16(acc[mf][nf], aH[mf], bL[nf]);
                    mma_bf16(acc[mf][nf], aH[mf], bH[nf]);
                }
        }
    };

    // ---- 2-stage pipeline ----
    loadAB(0);
    storeAB(0);
    __syncthreads();
    for (int it = 0; it < nIter; ++it) {
        int cur = it & 1;
        if (it + 1 < nIter) loadAB((it + 1) << 5);
        compute(cur);
        if (it + 1 < nIter) { storeAB(cur ^ 1); __syncthreads(); }
    }

    // ---- epilogue ----
    float* Cb = C + z * cstride + (size_t)bm * 128 * ldc + bn * 128;
#pragma unroll
    for (int mf = 0; mf < 4; mf++) {
        int row0 = wm + mf * 16 + g8;
        int row1 = row0 + 8;
#pragma unroll
        for (int nf = 0; nf < 4; nf++) {
            int col = wn + nf * 8 + tig * 2;
            *(float2*)(Cb + (size_t)row0 * ldc + col) =
                make_float2(acc[mf][nf][0] * alpha, acc[mf][nf][1] * alpha);
            *(float2*)(Cb + (size_t)row1 * ldc + col) =
                make_float2(acc[mf][nf][2] * alpha, acc[mf][nf][3] * alpha);
        }
    }
}

// =============================================================
// RMSNorm + RoPE: ONE WARP per (s, head). Pure warp shuffles.
// =============================================================
__global__ void rope2_kernel(float* __restrict__ buf, int rowstride, int nheads,
                             const float* __restrict__ gain)
{
    const int w    = blockIdx.x * (blockDim.x >> 5) + (threadIdx.x >> 5);
    const int lane = threadIdx.x & 31;
    const int s = w / nheads;
    const int h = w % nheads;
    if (s >= S_LEN) return;

    float* p = buf + (size_t)s * rowstride + h * HD;

    float2 u1 = *(const float2*)(p + 2 * lane);
    float2 u2 = *(const float2*)(p + 64 + 2 * lane);

    float ss = u1.x * u1.x + u1.y * u1.y + u2.x * u2.x + u2.y * u2.y;
#pragma unroll
    for (int off = 16; off; off >>= 1)
        ss += __shfl_xor_sync(0xffffffffu, ss, off);

    const float r = rsqrtf(ss * (1.f / 128.f) + 1.1920929e-07f);
    const float g = gain ? gain[h] : 1.0f;

    float x1a = u1.x * r, x1b = u1.y * r;
    float x2a = u2.x * r, x2b = u2.y * r;

    const float kln = 9.210340371976184f / 128.f;   // ln(10000)/128
    float th0 = (float)s * expf(-(float)(2 * (2 * lane))     * kln);
    float th1 = (float)s * expf(-(float)(2 * (2 * lane + 1)) * kln);
    float c0, s0, c1, s1;
    sincosf(th0, &s0, &c0);
    sincosf(th1, &s1, &c1);

    float o1a = x1a * c0 + x2a * s0;
    float o1b = x1b * c1 + x2b * s1;
    float o2a = x2a * c0 - x1a * s0;
    float o2b = x2b * c1 - x1b * s1;

    *(float2*)(p + 2 * lane)      = make_float2(o1a * g, o1b * g);
    *(float2*)(p + 64 + 2 * lane) = make_float2(o2a * g, o2b * g);
}

// =============================================================
// Softmax per (row i, head h) over j in [0, i]; zero tail out to
// the row's 128-tile boundary so PV's triangular K-limit is safe.
// =============================================================
__global__ void __launch_bounds__(128)
softmax_kernel()
{
    const int i = blockIdx.x;
    const int h = blockIdx.y;
    float* base = g_s + ((size_t)h * S_LEN + i) * S_LEN;
    const int n = i + 1;

    const int tid = threadIdx.x;
    const int lane = tid & 31, w = tid >> 5;
    __shared__ float red[4];

    float m = -INFINITY;
    for (int j = tid; j < n; j += 128) m = fmaxf(m, base[j]);
#pragma unroll
    for (int off = 16; off; off >>= 1)
        m = fmaxf(m, __shfl_xor_sync(0xffffffffu, m, off));
    if (lane == 0) red[w] = m;
    __syncthreads();
    m = fmaxf(fmaxf(red[0], red[1]), fmaxf(red[2], red[3]));
    __syncthreads();

    float sum = 0.f;
    for (int j = tid; j < n; j += 128) sum += expf(base[j] - m);
#pragma unroll
    for (int off = 16; off; off >>= 1)
        sum += __shfl_xor_sync(0xffffffffu, sum, off);
    if (lane == 0) red[w] = sum;
    __syncthreads();
    const float inv = 1.f / (red[0] + red[1] + red[2] + red[3]);

    for (int j = tid; j < n; j += 128) base[j] = expf(base[j] - m) * inv;

    // zero tail out to the 128-tile boundary (PV reads k < (bm+1)*128)
    const int te = ((i >> 7) + 1) << 7;
    for (int j = n + tid; j < te; j += 128) base[j] = 0.f;
}

// =============================================================
// v-direction rejection, in place on g_y. One warp per (s, h).
// =============================================================
__global__ void reject_kernel()
{
    const int w    = blockIdx.x * (blockDim.x >> 5) + (threadIdx.x >> 5);
    const int lane = threadIdx.x & 31;
    const int s = w >> 4;
    const int h = w & 15;
    if (s >= S_LEN) return;

    const int kv = h >> 2;
    float* yp = g_y + (size_t)s * DMODEL + h * HD;
    const float* vp = g_v + (size_t)s * KVD + kv * HD;

    float4 vv = *(const float4*)(vp + lane * 4);
    float4 yy = *(const float4*)(yp + lane * 4);
    float vsq = vv.x * vv.x + vv.y * vv.y + vv.z * vv.z + vv.w * vv.w;
    float yv  = yy.x * vv.x + yy.y * vv.y + yy.z * vv.z + yy.w * vv.w;
#pragma unroll
    for (int off = 16; off; off >>= 1) {
        vsq += __shfl_xor_sync(0xffffffffu, vsq, off);
        yv  += __shfl_xor_sync(0xffffffffu, yv, off);
    }
    float mx = fmaxf(sqrtf(vsq), 1e-12f);
    float c2 = yv / (mx * mx);
    yy.x -= c2 * vv.x; yy.y -= c2 * vv.y;
    yy.z -= c2 * vv.z; yy.w -= c2 * vv.w;
    *(float4*)(yp + lane * 4) = yy;
}

// =============================================================
// v output transpose: [S][KV*128] -> [KV][S][128]
// =============================================================
__global__ void v_transpose_kernel(const float* __restrict__ v, float* __restrict__ out)
{
    int idx = blockIdx.x * blockDim.x + threadIdx.x;
    if (idx < S_LEN * KVD / 4) {
        int f = idx * 4;
        int s = f / KVD;
        int rem = f % KVD;
        int kvh = rem / HD;
        int d = rem % HD;
        float4 val = *(const float4*)(v + f);
        *(float4*)(out + (size_t)kvh * S_LEN * HD + (size_t)s * HD + d) = val;
    }
}

// =============================================================
// launch — input identification by size signature (see R2 notes).
// =============================================================
extern "C" void kernel_launch(void* const* d_in, const int* in_sizes, int n_in,
                              void* d_out, int out_size)
{
    int big[3], nbig = 0;
    int med[2], nmed = 0;
    int gidx = -1;
    for (int i = 0; i < n_in && i < 6; i++) {
        int sz = in_sizes[i];
        if (sz == NHEADS)                 gidx = i;
        else if (sz == S_LEN * KVD)       { if (nmed < 2) med[nmed++] = i; }
        else                              { if (nbig < 3) big[nbig++] = i; }
    }
    int ix, iwq, iwk, iwv, iwp, ig;
    ig  = (gidx >= 0) ? gidx : 5;
    iwk = (nmed > 0) ? med[0] : 2;
    iwv = (nmed > 1) ? med[1] : 3;
    if (ig == 5) {          // dict / signature order: x, Wq, ..., Wp
        ix  = (nbig > 0) ? big[0] : 0;
        iwq = (nbig > 1) ? big[1] : 1;
        iwp = (nbig > 2) ? big[2] : 4;
    } else {                // alphabetical: Wk, Wp, Wq, Wv, q_gain, x
        iwp = (nbig > 0) ? big[0] : 1;
        iwq = (nbig > 1) ? big[1] : 2;
        ix  = (nbig > 2) ? big[2] : 5;
    }

    const float* x  = (const float*)d_in[ix];
    const float* Wq = (const float*)d_in[iwq];
    const float* Wk = (const float*)d_in[iwk];
    const float* Wv = (const float*)d_in[iwv];
    const float* Wp = (const float*)d_in[iwp];
    const float* qg = (const float*)d_in[ig];
    float* out = (float*)d_out;

    float *pq, *pk, *pv, *py, *ps;
    cudaGetSymbolAddress((void**)&pq, g_q);
    cudaGetSymbolAddress((void**)&pk, g_k);
    cudaGetSymbolAddress((void**)&pv, g_v);
    cudaGetSymbolAddress((void**)&py, g_y);
    cudaGetSymbolAddress((void**)&ps, g_s);

    cudaFuncSetAttribute(gemm_bf16x3_kernel,
                         cudaFuncAttributeMaxDynamicSharedMemorySize, GSMEM_BYTES);
    (void)cudaGetLastError();   // clear any sticky state; attribute set is idempotent

    const float scale = 0.08838834764831845f;   // 1/sqrt(128)

    // projections (NT): C = A * W^T
    gemm_bf16x3_kernel<<<dim3(DMODEL / 128, S_LEN / 128, 1), 256, GSMEM_BYTES>>>(
        x, Wq, pq, S_LEN, DMODEL, DMODEL, DMODEL, DMODEL, DMODEL,
        0, 0, 0, 0, 1.0f, 0);
    gemm_bf16x3_kernel<<<dim3(KVD / 128, S_LEN / 128, 1), 256, GSMEM_BYTES>>>(
        x, Wk, pk, S_LEN, KVD, DMODEL, DMODEL, DMODEL, KVD,
        0, 0, 0, 0, 1.0f, 0);
    gemm_bf16x3_kernel<<<dim3(KVD / 128, S_LEN / 128, 1), 256, GSMEM_BYTES>>>(
        x, Wv, pv, S_LEN, KVD, DMODEL, DMODEL, DMODEL, KVD,
        0, 0, 0, 0, 1.0f, 0);

    // rmsnorm + rope (+ gain on q)
    rope2_kernel<<<(S_LEN * NHEADS) / 4, 128>>>(pq, DMODEL, NHEADS, qg);
    rope2_kernel<<<(S_LEN * KVH)    / 4, 128>>>(pk, KVD,    KVH,    nullptr);

    // scores (NT, batched over 16 heads, causal tile skip):
    //   S[h] = scale * Q[:, h*128:...] @ K[:, (h>>2)*128:...]^T
    gemm_bf16x3_kernel<<<dim3(S_LEN / 128, S_LEN / 128, NHEADS), 256, GSMEM_BYTES>>>(
        pq, pk, ps, S_LEN, S_LEN, HD, DMODEL, KVD, S_LEN,
        (size_t)HD, (size_t)HD, (size_t)S_LEN * S_LEN, 2, scale, 2);

    // softmax (causal rows)
    softmax_kernel<<<dim3(S_LEN, NHEADS), 128>>>();

    // PV (NN, batched, triangular K-limit): Y[:, h*128:] = P[h] @ V[:, (h>>2)*128:]
    gemm_bf16x3_kernel<<<dim3(HD / 128, S_LEN / 128, NHEADS), 256, GSMEM_BYTES>>>(
        ps, pv, py, S_LEN, HD, S_LEN, S_LEN, KVD, DMODEL,
        (size_t)S_LEN * S_LEN, (size_t)HD, (size_t)HD, 2, 1.0f, 1 | 4);

    // v-rejection (in place on g_y)
    reject_kernel<<<(S_LEN * NHEADS) / 4, 128>>>();

    // output projection (NT)
    gemm_bf16x3_kernel<<<dim3(DMODEL / 128, S_LEN / 128, 1), 256, GSMEM_BYTES>>>(
        py, Wp, out, S_LEN, DMODEL, DMODEL, DMODEL, DMODEL, DMODEL,
        0, 0, 0, 0, 1.0f, 0);

    // v second output
    if (out_size >= S_LEN * DMODEL + S_LEN * KVD)
        v_transpose_kernel<<<(S_LEN * KVD / 4 + 255) / 256, 256>>>(pv, out + (size_t)S_LEN * DMODEL);
}